// round 16
// baseline (speedup 1.0000x reference)
#include <cuda_runtime.h>
#include <cuda_bf16.h>
#include <cstdint>

#define BB 4096
#define SS 128
#define EH 128
#define DH 256
#define NDEC 10

typedef unsigned long long u64;

__device__ float g_ctx[BB * EH];
__device__ float g_gates[BB * 768];
__device__ float g_gi0[BB * 768];
__device__ float g_h[BB * DH];
__device__ __nv_bfloat16 g_hb_hi[BB * DH];
__device__ __nv_bfloat16 g_hb_lo[BB * DH];
__device__ __nv_bfloat16 g_wb_hi[768 * DH];
__device__ __nv_bfloat16 g_wb_lo[768 * DH];

__device__ __forceinline__ void ffma2(u64 a, u64 b, u64& c) {
    asm("fma.rn.f32x2 %0, %1, %2, %0;" : "+l"(c) : "l"(a), "l"(b));
}
__device__ __forceinline__ float f2sum(u64 a) {
    float lo = __int_as_float((unsigned)(a & 0xffffffffULL));
    float hi = __int_as_float((unsigned)(a >> 32));
    return lo + hi;
}
__device__ __forceinline__ float sigf(float v) {
    return __fdividef(1.f, 1.f + __expf(-v));
}
__device__ __forceinline__ float tanhfast(float v) {
    float e = __expf(2.f * v);
    return 1.f - __fdividef(2.f, e + 1.f);
}
__device__ __forceinline__ unsigned smem_u32(const void* p) {
    return (unsigned)__cvta_generic_to_shared(p);
}
__device__ __forceinline__ void ldsm_x4(uint32_t* r, unsigned addr) {
    asm volatile("ldmatrix.sync.aligned.m8n8.x4.shared.b16 {%0,%1,%2,%3}, [%4];"
                 : "=r"(r[0]), "=r"(r[1]), "=r"(r[2]), "=r"(r[3]) : "r"(addr));
}
__device__ __forceinline__ void ldsm_x2(uint32_t* r, unsigned addr) {
    asm volatile("ldmatrix.sync.aligned.m8n8.x2.shared.b16 {%0,%1}, [%2];"
                 : "=r"(r[0]), "=r"(r[1]) : "r"(addr));
}
__device__ __forceinline__ void mma_bf16(float* c, const uint32_t* a, const uint32_t* b) {
    asm volatile(
        "mma.sync.aligned.m16n8k16.row.col.f32.bf16.bf16.f32 "
        "{%0,%1,%2,%3}, {%4,%5,%6,%7}, {%8,%9}, {%0,%1,%2,%3};"
        : "+f"(c[0]), "+f"(c[1]), "+f"(c[2]), "+f"(c[3])
        : "r"(a[0]), "r"(a[1]), "r"(a[2]), "r"(a[3]), "r"(b[0]), "r"(b[1]));
}
__device__ __forceinline__ uint32_t pack2_bf16(float a, float b) {
    return (uint32_t)__bfloat16_as_ushort(__float2bfloat16_rn(a)) |
           ((uint32_t)__bfloat16_as_ushort(__float2bfloat16_rn(b)) << 16);
}
#define SW128(x) ((x) ^ (((x) >> 3) & 0x70))

// ---------------------------------------------------------------------------
// Encoder (tensor-core): R14 structure (256 thr, ldsm_x2 B) + hoisted
// swizzle algebra: SW128(row*128 + koff) = SWbase(row) + (koff ^ mask(row)).
// ---------------------------------------------------------------------------
#define E_RPB 28
#define EA_HI 0
#define EA_LO 8192
#define EB_HI 16384
#define EB_LO 114688
#define E_WIH 212992
#define E_BIAS 220672
#define E_XS 222720
#define E2_SMEM_BYTES 224000

__global__ void __launch_bounds__(256, 1)
enc_tc_kernel(const float* __restrict__ x, const float* __restrict__ Wih,
              const float* __restrict__ Whh, const float* __restrict__ bih,
              const float* __restrict__ bhh)
{
    extern __shared__ char smem[];
    const unsigned sb = smem_u32(smem);
    float* WihS = (float*)(smem + E_WIH);
    float* bias = (float*)(smem + E_BIAS);
    float* xsb  = (float*)(smem + E_XS);

    const int tid = threadIdx.x;
    const int lane = tid & 31;
    const int w = tid >> 5;
    const int b0 = blockIdx.x * E_RPB;

    for (int u = tid; u < 4096; u += 256) ((uint32_t*)smem)[u] = 0u;
    for (int u = tid; u < 384 * 64; u += 256) {
        int c = u >> 6, kp = u & 63;
        float2 v = *(const float2*)(Whh + (long)c * 128 + kp * 2);
        float h0 = __bfloat162float(__float2bfloat16_rn(v.x));
        float h1 = __bfloat162float(__float2bfloat16_rn(v.y));
        int slab = kp >> 5;
        unsigned byte = (unsigned)(c * 128 + (kp & 31) * 4);
        unsigned sw = SW128(byte);
        *(uint32_t*)(smem + EB_HI + slab * 49152 + sw) = pack2_bf16(h0, h1);
        *(uint32_t*)(smem + EB_LO + slab * 49152 + sw) = pack2_bf16(v.x - h0, v.y - h1);
    }
    for (int u = tid; u < 384 * 5; u += 256) WihS[u] = Wih[u];
    if (tid < 128) {
        bias[tid]       = bih[tid] + bhh[tid];
        bias[128 + tid] = bih[128 + tid] + bhh[128 + tid];
        bias[256 + tid] = bih[256 + tid];
        bias[384 + tid] = bhh[256 + tid];
    }
    if (tid < 160) {
        int row = tid / 5, b = b0 + row;
        xsb[tid] = (row < E_RPB && b < BB) ? x[(long)b * (SS * 5) + (tid % 5)] : 0.f;
    }
    __syncthreads();

    int cl[2][2];
    float c_bsr[2][2], c_bsz[2][2], c_bin[2][2], c_bhn[2][2];
#pragma unroll
    for (int nf = 0; nf < 2; nf++)
#pragma unroll
        for (int j = 0; j < 2; j++) {
            int c = w * 16 + nf * 8 + (lane & 3) * 2 + j;
            cl[nf][j] = c;
            c_bsr[nf][j] = bias[c];
            c_bsz[nf][j] = bias[128 + c];
            c_bin[nf][j] = bias[256 + c];
            c_bhn[nf][j] = bias[384 + c];
        }

    float hold[2][2][2][2];
#pragma unroll
    for (int a = 0; a < 2; a++)
#pragma unroll
        for (int b_ = 0; b_ < 2; b_++)
#pragma unroll
            for (int c = 0; c < 2; c++)
#pragma unroll
                for (int d = 0; d < 2; d++) hold[a][b_][c][d] = 0.f;

    const unsigned a_koff_half = (unsigned)((lane >> 4) * 16);
    const unsigned b_koff_half = (unsigned)(((lane >> 3) & 1) * 16);

    // hoisted swizzle bases/masks (loop-invariant across t and kk)
    unsigned baseA[2], maskA[2];
#pragma unroll
    for (int mf = 0; mf < 2; mf++) {
        unsigned R = (unsigned)((mf * 16 + (lane & 15)) * 128);
        maskA[mf] = (R >> 3) & 0x70;
        baseA[mf] = sb + EA_HI + R;       // R has bits 4-6 clear -> SW(R)=R
    }
    unsigned baseB[3][2], maskB[3][2];
#pragma unroll
    for (int g = 0; g < 3; g++)
#pragma unroll
        for (int nf = 0; nf < 2; nf++) {
            unsigned R = (unsigned)((g * 128 + w * 16 + nf * 8 + (lane & 7)) * 128);
            maskB[g][nf] = (R >> 3) & 0x70;
            baseB[g][nf] = sb + EB_HI + R;
        }
    // h-write addresses (fully t-invariant)
    unsigned wrA[2][2][2];
#pragma unroll
    for (int mf = 0; mf < 2; mf++)
#pragma unroll
        for (int qr = 0; qr < 2; qr++)
#pragma unroll
            for (int nf = 0; nf < 2; nf++) {
                int row = mf * 16 + (lane >> 2) + qr * 8;
                int c0 = cl[nf][0];
                unsigned byte = (unsigned)(row * 128 + (c0 & 63) * 2);
                wrA[mf][qr][nf] = sb + EA_HI + (unsigned)((c0 >> 6) * 4096) + SW128(byte);
            }

    for (int t = 0; t < SS; ++t) {
        float cfr[2][3][2][4];
#pragma unroll
        for (int mf = 0; mf < 2; mf++)
#pragma unroll
            for (int g = 0; g < 3; g++)
#pragma unroll
                for (int nf = 0; nf < 2; nf++)
#pragma unroll
                    for (int q = 0; q < 4; q++) cfr[mf][g][nf][q] = 0.f;

#pragma unroll
        for (int kk = 0; kk < 8; ++kk) {
            const unsigned aslab = (unsigned)((kk >> 2) * 4096);
            const unsigned bslab = (unsigned)((kk >> 2) * 49152);
            const unsigned akoff = (unsigned)((kk & 3) * 32) + a_koff_half;
            const unsigned bkoff = (unsigned)((kk & 3) * 32) + b_koff_half;
            uint32_t ah[2][4], al[2][4];
#pragma unroll
            for (int mf = 0; mf < 2; mf++) {
                unsigned ad = baseA[mf] + aslab + (akoff ^ maskA[mf]);
                ldsm_x4(ah[mf], ad);
                ldsm_x4(al[mf], ad + (EA_LO - EA_HI));
            }
#pragma unroll
            for (int g = 0; g < 3; g++)
#pragma unroll
                for (int nf = 0; nf < 2; nf++) {
                    unsigned bd = baseB[g][nf] + bslab + (bkoff ^ maskB[g][nf]);
                    uint32_t bh[2], bl[2];
                    ldsm_x2(bh, bd);
                    ldsm_x2(bl, bd + (EB_LO - EB_HI));
#pragma unroll
                    for (int mf = 0; mf < 2; mf++) {
                        mma_bf16(cfr[mf][g][nf], ah[mf], bh);
                        mma_bf16(cfr[mf][g][nf], ah[mf], bl);
                        mma_bf16(cfr[mf][g][nf], al[mf], bh);
                    }
                }
        }

        const float* xs = xsb + (t & 1) * 160;
#pragma unroll
        for (int mf = 0; mf < 2; mf++) {
#pragma unroll
            for (int qr = 0; qr < 2; qr++) {
                int row = mf * 16 + (lane >> 2) + qr * 8;
                float xv[5];
#pragma unroll
                for (int j = 0; j < 5; j++) xv[j] = xs[row * 5 + j];
#pragma unroll
                for (int nf = 0; nf < 2; nf++)
#pragma unroll
                    for (int j = 0; j < 2; j++) {
                        int c = cl[nf][j];
                        int q = qr * 2 + j;
                        float gr = cfr[mf][0][nf][q] + c_bsr[nf][j];
                        float gz = cfr[mf][1][nf][q] + c_bsz[nf][j];
                        float ghn = cfr[mf][2][nf][q] + c_bhn[nf][j];
                        float gn = c_bin[nf][j];
#pragma unroll
                        for (int jj = 0; jj < 5; jj++) {
                            gr += xv[jj] * WihS[c * 5 + jj];
                            gz += xv[jj] * WihS[(c + 128) * 5 + jj];
                            gn += xv[jj] * WihS[(c + 256) * 5 + jj];
                        }
                        float rr = sigf(gr);
                        float zz = sigf(gz);
                        float nn = tanhfast(gn + rr * ghn);
                        hold[mf][nf][qr][j] =
                            (1.f - zz) * nn + zz * hold[mf][nf][qr][j];
                    }
            }
        }

        if (t + 1 < SS && tid < 160) {
            int row = tid / 5, b = b0 + row;
            xsb[((t + 1) & 1) * 160 + tid] =
                (row < E_RPB && b < BB) ? x[(long)b * (SS * 5) + (t + 1) * 5 + (tid % 5)]
                                        : 0.f;
        }
        __syncthreads();

#pragma unroll
        for (int mf = 0; mf < 2; mf++)
#pragma unroll
            for (int qr = 0; qr < 2; qr++)
#pragma unroll
                for (int nf = 0; nf < 2; nf++) {
                    float h0 = hold[mf][nf][qr][0], h1 = hold[mf][nf][qr][1];
                    float h0h = __bfloat162float(__float2bfloat16_rn(h0));
                    float h1h = __bfloat162float(__float2bfloat16_rn(h1));
                    unsigned ad = wrA[mf][qr][nf];
                    *(uint32_t*)(smem + (ad - sb)) = pack2_bf16(h0h, h1h);
                    *(uint32_t*)(smem + (ad - sb) + (EA_LO - EA_HI)) =
                        pack2_bf16(h0 - h0h, h1 - h1h);
                }
        __syncthreads();
    }

#pragma unroll
    for (int mf = 0; mf < 2; mf++)
#pragma unroll
        for (int qr = 0; qr < 2; qr++) {
            int row = mf * 16 + (lane >> 2) + qr * 8;
            if (row < E_RPB && b0 + row < BB) {
#pragma unroll
                for (int nf = 0; nf < 2; nf++) {
                    *(float2*)(g_ctx + (long)(b0 + row) * 128 + cl[nf][0]) =
                        make_float2(hold[mf][nf][qr][0], hold[mf][nf][qr][1]);
                }
            }
        }
}

// ---------------------------------------------------------------------------
// init
// ---------------------------------------------------------------------------
__global__ void init_kernel(const float* __restrict__ Whh, float* __restrict__ out) {
    const float4 one4 = make_float4(1.f, 1.f, 1.f, 1.f);
    int i = blockIdx.x * blockDim.x + threadIdx.x;
    if (i < BB * DH / 4) ((float4*)g_h)[i] = one4;
    if (i < BB * DH) {
        g_hb_hi[i] = __float2bfloat16(1.f);
        g_hb_lo[i] = __float2bfloat16(0.f);
    }
    if (i < 768 * DH) {
        float w = Whh[i];
        __nv_bfloat16 hi = __float2bfloat16(w);
        g_wb_hi[i] = hi;
        g_wb_lo[i] = __float2bfloat16(w - __bfloat162float(hi));
    }
    if (i < BB * 118) {
        int b = i / 118, tt = i % 118 + NDEC;
        *(float4*)(out + (long)b * (SS * 4) + tt * 4) = one4;
    }
}

// ---------------------------------------------------------------------------
// gi0 (once), scalar
// ---------------------------------------------------------------------------
#define NG 24
#define RPG 171
#define GI_WSTR 132
#define GI_SMEM_BYTES ((128 * GI_WSTR + 64 * 128) * 4)

__global__ void __launch_bounds__(256, 1)
dec_gi0_kernel(const float* __restrict__ Wih, const float* __restrict__ bih)
{
    extern __shared__ float sm[];
    float* Ws = sm;
    float* hs = sm + 128 * GI_WSTR;

    const int tid = threadIdx.x;
    const int s = blockIdx.x / NG;
    const int g = blockIdx.x % NG;
    const int r0 = g * RPG;
    const int nr = min(RPG, BB - r0);

    for (int u = tid; u < 128 * 128; u += 256) {
        int c = u >> 7, k = u & 127;
        Ws[c * GI_WSTR + k] = Wih[(long)(s * 128 + c) * 129 + k];
    }
    __syncthreads();

    const int rg = tid >> 5, cg = tid & 31;
    float bv[4];
#pragma unroll
    for (int m = 0; m < 4; m++) bv[m] = bih[s * 128 + cg + 32 * m];

    const int nchunk = (nr + 63) >> 6;
    for (int ch = 0; ch < nchunk; ++ch) {
        int rbase = ch * 64;
        for (int u = tid; u < 64 * 32; u += 256) {
            int r = u >> 5, q = u & 31;
            float4 v = make_float4(0.f, 0.f, 0.f, 0.f);
            if (rbase + r < nr)
                v = *(const float4*)(g_ctx + (long)(r0 + rbase + r) * 128 + q * 4);
            *(float4*)(hs + r * 128 + q * 4) = v;
        }
        __syncthreads();

        u64 acc[8][4];
#pragma unroll
        for (int i = 0; i < 8; i++)
#pragma unroll
            for (int m = 0; m < 4; m++) acc[i][m] = 0ULL;

#pragma unroll 2
        for (int kq = 0; kq < 32; ++kq) {
            ulonglong2 w[4];
#pragma unroll
            for (int m = 0; m < 4; m++)
                w[m] = *(const ulonglong2*)(Ws + (cg + 32 * m) * GI_WSTR + kq * 4);
#pragma unroll
            for (int i = 0; i < 8; i++) {
                ulonglong2 hv = *(const ulonglong2*)(hs + (rg * 8 + i) * 128 + kq * 4);
#pragma unroll
                for (int m = 0; m < 4; m++) {
                    ffma2(hv.x, w[m].x, acc[i][m]);
                    ffma2(hv.y, w[m].y, acc[i][m]);
                }
            }
        }
#pragma unroll
        for (int i = 0; i < 8; i++) {
            int row = rbase + rg * 8 + i;
            if (row < nr) {
#pragma unroll
                for (int m = 0; m < 4; m++)
                    g_gi0[(long)(r0 + row) * 768 + s * 128 + cg + 32 * m] =
                        f2sum(acc[i][m]) + bv[m];
            }
        }
        __syncthreads();
    }
}

// ---------------------------------------------------------------------------
// Decoder GEMM via mma.sync. R13/R14 (kept): k-chunked (2 x k=128),
// 2 blocks/SM, 512 threads, warp tile 32x16, ldsm_x2 B. Grid 384.
// ---------------------------------------------------------------------------
#define MM_STR 136
#define MM_A_HI 0
#define MM_A_LO (MM_A_HI + 128 * MM_STR * 2)
#define MM_B_HI (MM_A_LO + 128 * MM_STR * 2)
#define MM_B_LO (MM_B_HI + 64 * MM_STR * 2)
#define MM_SMEM_BYTES (MM_B_LO + 64 * MM_STR * 2)

__global__ void __launch_bounds__(512, 2)
dec_gemm_mma_kernel()
{
    extern __shared__ char smem[];
    const unsigned sb = smem_u32(smem);
    const int tid = threadIdx.x;
    const int lane = tid & 31;
    const int wid = tid >> 5;
    const int warp_m = wid & 3;
    const int warp_n = wid >> 2;
    const int mt = blockIdx.x & 31;
    const int nt = blockIdx.x >> 5;
    const int r0 = mt * 128;
    const int n0 = nt * 64;

    float c[2][2][4];
#pragma unroll
    for (int mf = 0; mf < 2; mf++)
#pragma unroll
        for (int nf = 0; nf < 2; nf++)
#pragma unroll
            for (int q = 0; q < 4; q++) c[mf][nf][q] = 0.f;

    const unsigned a_row = (unsigned)(warp_m * 32 + (lane & 15));
    const unsigned a_half = (unsigned)((lane >> 4) * 16);
    const unsigned b_row = (unsigned)(warp_n * 16 + (lane & 7));
    const unsigned b_half = (unsigned)(((lane >> 3) & 1) * 16);

    for (int kc = 0; kc < 2; ++kc) {
        for (int u = tid; u < 128 * 16; u += 512) {
            int row = u >> 4, seg = u & 15;
            unsigned off = (unsigned)(row * (MM_STR * 2) + seg * 16);
            long src = (long)(r0 + row) * 256 + kc * 128 + seg * 8;
            *(uint4*)(smem + MM_A_HI + off) = *(const uint4*)(g_hb_hi + src);
            *(uint4*)(smem + MM_A_LO + off) = *(const uint4*)(g_hb_lo + src);
        }
        for (int u = tid; u < 64 * 16; u += 512) {
            int row = u >> 4, seg = u & 15;
            unsigned off = (unsigned)(row * (MM_STR * 2) + seg * 16);
            long src = (long)(n0 + row) * 256 + kc * 128 + seg * 8;
            *(uint4*)(smem + MM_B_HI + off) = *(const uint4*)(g_wb_hi + src);
            *(uint4*)(smem + MM_B_LO + off) = *(const uint4*)(g_wb_lo + src);
        }
        __syncthreads();

#pragma unroll 4
        for (int kk = 0; kk < 8; ++kk) {
            const unsigned koff = (unsigned)(kk * 32);
            uint32_t bh[2][2], bl[2][2];
#pragma unroll
            for (int nf = 0; nf < 2; nf++) {
                unsigned ba = (b_row + nf * 8) * (MM_STR * 2) + koff + b_half;
                ldsm_x2(bh[nf], sb + MM_B_HI + ba);
                ldsm_x2(bl[nf], sb + MM_B_LO + ba);
            }
#pragma unroll
            for (int mf = 0; mf < 2; mf++) {
                unsigned aa = (a_row + mf * 16) * (MM_STR * 2) + koff + a_half;
                uint32_t ah[4], al[4];
                ldsm_x4(ah, sb + MM_A_HI + aa);
                ldsm_x4(al, sb + MM_A_LO + aa);
#pragma unroll
                for (int nf = 0; nf < 2; nf++) {
                    mma_bf16(c[mf][nf], ah, bh[nf]);
                    mma_bf16(c[mf][nf], ah, bl[nf]);
                    mma_bf16(c[mf][nf], al, bh[nf]);
                }
            }
        }
        __syncthreads();
    }

#pragma unroll
    for (int mf = 0; mf < 2; mf++) {
#pragma unroll
        for (int nf = 0; nf < 2; nf++) {
            int row = r0 + warp_m * 32 + mf * 16 + (lane >> 2);
            int col = n0 + warp_n * 16 + nf * 8 + (lane & 3) * 2;
            *(float2*)(g_gates + (long)row * 768 + col) =
                make_float2(c[mf][nf][0], c[mf][nf][1]);
            *(float2*)(g_gates + (long)(row + 8) * 768 + col) =
                make_float2(c[mf][nf][2], c[mf][nf][3]);
        }
    }
}

// ---------------------------------------------------------------------------
// pointwise
// ---------------------------------------------------------------------------
__global__ void __launch_bounds__(256, 1)
dec_point_kernel(const float* __restrict__ y, const float* __restrict__ Wih,
                 const float* __restrict__ bhh, const float* __restrict__ linW,
                 const float* __restrict__ linb, float* __restrict__ out, int t)
{
    __shared__ float hs[32 * 256];
    __shared__ float ys[32];
    __shared__ float lw[1024];
    __shared__ float lb[4];

    const int tid = threadIdx.x;
    const int b0 = blockIdx.x * 32;

    if (tid < 32) ys[tid] = y[(long)(b0 + tid) * SS + t];
    for (int u = tid; u < 1024; u += 256) lw[u] = linW[u];
    if (tid < 4) lb[tid] = linb[tid];

    const int c = tid;
    const float wyr = Wih[(long)c * 129 + 128];
    const float wyz = Wih[(long)(c + 256) * 129 + 128];
    const float wyn = Wih[(long)(c + 512) * 129 + 128];
    const float br = bhh[c], bz = bhh[c + 256], bn = bhh[c + 512];
    __syncthreads();

#pragma unroll 4
    for (int r = 0; r < 32; ++r) {
        long b = b0 + r;
        float yv = ys[r];
        float gr  = g_gi0[b * 768 + c]       + yv * wyr + g_gates[b * 768 + c]       + br;
        float gz  = g_gi0[b * 768 + c + 256] + yv * wyz + g_gates[b * 768 + c + 256] + bz;
        float gni = g_gi0[b * 768 + c + 512] + yv * wyn;
        float gnh = g_gates[b * 768 + c + 512] + bn;
        float rr = sigf(gr);
        float zz = sigf(gz);
        float nn = tanhfast(gni + rr * gnh);
        float h  = g_h[b * 256 + c];
        float hn = (1.f - zz) * nn + zz * h;
        g_h[b * 256 + c] = hn;
        __nv_bfloat16 hi = __float2bfloat16(hn);
        g_hb_hi[b * 256 + c] = hi;
        g_hb_lo[b * 256 + c] = __float2bfloat16(hn - __bfloat162float(hi));
        hs[r * 256 + c] = hn;
    }
    __syncthreads();

    if (tid < 128) {
        int r = tid >> 2, o = tid & 3;
        float s = lb[o];
#pragma unroll 4
        for (int q = 0; q < 64; ++q) {
            float4 hv = *(float4*)(hs + r * 256 + q * 4);
            float4 wv = *(float4*)(lw + o * 256 + q * 4);
            s += hv.x * wv.x + hv.y * wv.y + hv.z * wv.z + hv.w * wv.w;
        }
        out[(long)(b0 + r) * (SS * 4) + t * 4 + o] = s;
    }
}

// pads: ncu captures launch #4 -> enc
__global__ void padA_kernel() {}
__global__ void padB_kernel() {}

extern "C" void kernel_launch(void* const* d_in, const int* in_sizes, int n_in,
                              void* d_out, int out_size) {
    const float* x    = (const float*)d_in[0];
    const float* y    = (const float*)d_in[1];
    const float* eWih = (const float*)d_in[2];
    const float* eWhh = (const float*)d_in[3];
    const float* ebih = (const float*)d_in[4];
    const float* ebhh = (const float*)d_in[5];
    const float* dWih = (const float*)d_in[6];
    const float* dWhh = (const float*)d_in[7];
    const float* dbih = (const float*)d_in[8];
    const float* dbhh = (const float*)d_in[9];
    const float* lW   = (const float*)d_in[10];
    const float* lb   = (const float*)d_in[11];
    float* out = (float*)d_out;

    cudaFuncSetAttribute(enc_tc_kernel, cudaFuncAttributeMaxDynamicSharedMemorySize,
                         E2_SMEM_BYTES);
    cudaFuncSetAttribute(dec_gi0_kernel, cudaFuncAttributeMaxDynamicSharedMemorySize,
                         GI_SMEM_BYTES);
    cudaFuncSetAttribute(dec_gemm_mma_kernel, cudaFuncAttributeMaxDynamicSharedMemorySize,
                         MM_SMEM_BYTES);

    init_kernel<<<BB, 256>>>(dWhh, out);                          // 1
    padA_kernel<<<1, 32>>>();                                     // 2
    padB_kernel<<<1, 32>>>();                                     // 3
    enc_tc_kernel<<<(BB + E_RPB - 1) / E_RPB, 256, E2_SMEM_BYTES>>>(  // 4 <- ncu
        x, eWih, eWhh, ebih, ebhh);
    dec_gi0_kernel<<<6 * NG, 256, GI_SMEM_BYTES>>>(dWih, dbih);
    for (int t = 0; t < NDEC; ++t) {
        dec_gemm_mma_kernel<<<384, 512, MM_SMEM_BYTES>>>();
        dec_point_kernel<<<BB / 32, 256>>>(y, dWih, dbhh, lW, lb, out, t);
    }
}

// round 17
// speedup vs baseline: 1.5541x; 1.5541x over previous
#include <cuda_runtime.h>
#include <cuda_bf16.h>
#include <cstdint>

#define BB 4096
#define SS 128
#define EH 128
#define DH 256
#define NDEC 10

typedef unsigned long long u64;

__device__ float g_ctx[BB * EH];
__device__ float g_gates[BB * 768];
__device__ float g_gi0[BB * 768];
__device__ float g_h[BB * DH];
__device__ __nv_bfloat16 g_hb_hi[BB * DH];
__device__ __nv_bfloat16 g_hb_lo[BB * DH];
__device__ __nv_bfloat16 g_wb_hi[768 * DH];
__device__ __nv_bfloat16 g_wb_lo[768 * DH];

__device__ __forceinline__ void ffma2(u64 a, u64 b, u64& c) {
    asm("fma.rn.f32x2 %0, %1, %2, %0;" : "+l"(c) : "l"(a), "l"(b));
}
__device__ __forceinline__ float f2sum(u64 a) {
    float lo = __int_as_float((unsigned)(a & 0xffffffffULL));
    float hi = __int_as_float((unsigned)(a >> 32));
    return lo + hi;
}
__device__ __forceinline__ float sigf(float v) {
    return __fdividef(1.f, 1.f + __expf(-v));
}
__device__ __forceinline__ float tanhfast(float v) {
    float e = __expf(2.f * v);
    return 1.f - __fdividef(2.f, e + 1.f);
}
__device__ __forceinline__ unsigned smem_u32(const void* p) {
    return (unsigned)__cvta_generic_to_shared(p);
}
__device__ __forceinline__ void ldsm_x4(uint32_t* r, unsigned addr) {
    asm volatile("ldmatrix.sync.aligned.m8n8.x4.shared.b16 {%0,%1,%2,%3}, [%4];"
                 : "=r"(r[0]), "=r"(r[1]), "=r"(r[2]), "=r"(r[3]) : "r"(addr));
}
__device__ __forceinline__ void ldsm_x2(uint32_t* r, unsigned addr) {
    asm volatile("ldmatrix.sync.aligned.m8n8.x2.shared.b16 {%0,%1}, [%2];"
                 : "=r"(r[0]), "=r"(r[1]) : "r"(addr));
}
__device__ __forceinline__ void mma_bf16(float* c, const uint32_t* a, const uint32_t* b) {
    asm volatile(
        "mma.sync.aligned.m16n8k16.row.col.f32.bf16.bf16.f32 "
        "{%0,%1,%2,%3}, {%4,%5,%6,%7}, {%8,%9}, {%0,%1,%2,%3};"
        : "+f"(c[0]), "+f"(c[1]), "+f"(c[2]), "+f"(c[3])
        : "r"(a[0]), "r"(a[1]), "r"(a[2]), "r"(a[3]), "r"(b[0]), "r"(b[1]));
}
__device__ __forceinline__ uint32_t pack2_bf16(float a, float b) {
    return (uint32_t)__bfloat16_as_ushort(__float2bfloat16_rn(a)) |
           ((uint32_t)__bfloat16_as_ushort(__float2bfloat16_rn(b)) << 16);
}
#define SW128(x) ((x) ^ (((x) >> 3) & 0x70))

// ---------------------------------------------------------------------------
// Encoder (tensor-core): exact R14 form (measured best ~543us inside the
// 964.9us total). 147 blocks x 256 threads. DO NOT TOUCH (R15/R16 both lost).
// ---------------------------------------------------------------------------
#define E_RPB 28
#define EA_HI 0
#define EA_LO 8192
#define EB_HI 16384
#define EB_LO 114688
#define E_WIH 212992
#define E_BIAS 220672
#define E_XS 222720
#define E2_SMEM_BYTES 224000

__global__ void __launch_bounds__(256, 1)
enc_tc_kernel(const float* __restrict__ x, const float* __restrict__ Wih,
              const float* __restrict__ Whh, const float* __restrict__ bih,
              const float* __restrict__ bhh)
{
    extern __shared__ char smem[];
    const unsigned sb = smem_u32(smem);
    float* WihS = (float*)(smem + E_WIH);
    float* bias = (float*)(smem + E_BIAS);
    float* xsb  = (float*)(smem + E_XS);

    const int tid = threadIdx.x;
    const int lane = tid & 31;
    const int w = tid >> 5;
    const int b0 = blockIdx.x * E_RPB;

    for (int u = tid; u < 4096; u += 256) ((uint32_t*)smem)[u] = 0u;
    for (int u = tid; u < 384 * 64; u += 256) {
        int c = u >> 6, kp = u & 63;
        float2 v = *(const float2*)(Whh + (long)c * 128 + kp * 2);
        float h0 = __bfloat162float(__float2bfloat16_rn(v.x));
        float h1 = __bfloat162float(__float2bfloat16_rn(v.y));
        int slab = kp >> 5;
        unsigned byte = (unsigned)(c * 128 + (kp & 31) * 4);
        unsigned sw = SW128(byte);
        *(uint32_t*)(smem + EB_HI + slab * 49152 + sw) = pack2_bf16(h0, h1);
        *(uint32_t*)(smem + EB_LO + slab * 49152 + sw) = pack2_bf16(v.x - h0, v.y - h1);
    }
    for (int u = tid; u < 384 * 5; u += 256) WihS[u] = Wih[u];
    if (tid < 128) {
        bias[tid]       = bih[tid] + bhh[tid];
        bias[128 + tid] = bih[128 + tid] + bhh[128 + tid];
        bias[256 + tid] = bih[256 + tid];
        bias[384 + tid] = bhh[256 + tid];
    }
    if (tid < 160) {
        int row = tid / 5, b = b0 + row;
        xsb[tid] = (row < E_RPB && b < BB) ? x[(long)b * (SS * 5) + (tid % 5)] : 0.f;
    }
    __syncthreads();

    int cl[2][2];
    float c_bsr[2][2], c_bsz[2][2], c_bin[2][2], c_bhn[2][2];
#pragma unroll
    for (int nf = 0; nf < 2; nf++)
#pragma unroll
        for (int j = 0; j < 2; j++) {
            int c = w * 16 + nf * 8 + (lane & 3) * 2 + j;
            cl[nf][j] = c;
            c_bsr[nf][j] = bias[c];
            c_bsz[nf][j] = bias[128 + c];
            c_bin[nf][j] = bias[256 + c];
            c_bhn[nf][j] = bias[384 + c];
        }

    float hold[2][2][2][2];
#pragma unroll
    for (int a = 0; a < 2; a++)
#pragma unroll
        for (int b_ = 0; b_ < 2; b_++)
#pragma unroll
            for (int c = 0; c < 2; c++)
#pragma unroll
                for (int d = 0; d < 2; d++) hold[a][b_][c][d] = 0.f;

    const unsigned a_koff_half = (unsigned)((lane >> 4) * 16);
    const unsigned b_koff_half = (unsigned)(((lane >> 3) & 1) * 16);

    for (int t = 0; t < SS; ++t) {
        float cfr[2][3][2][4];
#pragma unroll
        for (int mf = 0; mf < 2; mf++)
#pragma unroll
            for (int g = 0; g < 3; g++)
#pragma unroll
                for (int nf = 0; nf < 2; nf++)
#pragma unroll
                    for (int q = 0; q < 4; q++) cfr[mf][g][nf][q] = 0.f;

#pragma unroll
        for (int kk = 0; kk < 8; ++kk) {
            const unsigned aslab = (unsigned)((kk >> 2) * 4096);
            const unsigned bslab = (unsigned)((kk >> 2) * 49152);
            const unsigned akoff = (unsigned)((kk & 3) * 32) + a_koff_half;
            const unsigned bkoff = (unsigned)((kk & 3) * 32) + b_koff_half;
            uint32_t ah[2][4], al[2][4];
#pragma unroll
            for (int mf = 0; mf < 2; mf++) {
                unsigned byte = (unsigned)((mf * 16 + (lane & 15)) * 128) + akoff;
                unsigned sw = SW128(byte);
                ldsm_x4(ah[mf], sb + EA_HI + aslab + sw);
                ldsm_x4(al[mf], sb + EA_LO + aslab + sw);
            }
#pragma unroll
            for (int g = 0; g < 3; g++)
#pragma unroll
                for (int nf = 0; nf < 2; nf++) {
                    unsigned byte =
                        (unsigned)((g * 128 + w * 16 + nf * 8 + (lane & 7)) * 128) + bkoff;
                    unsigned sw = SW128(byte);
                    uint32_t bh[2], bl[2];
                    ldsm_x2(bh, sb + EB_HI + bslab + sw);
                    ldsm_x2(bl, sb + EB_LO + bslab + sw);
#pragma unroll
                    for (int mf = 0; mf < 2; mf++) {
                        mma_bf16(cfr[mf][g][nf], ah[mf], bh);
                        mma_bf16(cfr[mf][g][nf], ah[mf], bl);
                        mma_bf16(cfr[mf][g][nf], al[mf], bh);
                    }
                }
        }

        const float* xs = xsb + (t & 1) * 160;
#pragma unroll
        for (int mf = 0; mf < 2; mf++) {
#pragma unroll
            for (int qr = 0; qr < 2; qr++) {
                int row = mf * 16 + (lane >> 2) + qr * 8;
                float xv[5];
#pragma unroll
                for (int j = 0; j < 5; j++) xv[j] = xs[row * 5 + j];
#pragma unroll
                for (int nf = 0; nf < 2; nf++)
#pragma unroll
                    for (int j = 0; j < 2; j++) {
                        int c = cl[nf][j];
                        int q = qr * 2 + j;
                        float gr = cfr[mf][0][nf][q] + c_bsr[nf][j];
                        float gz = cfr[mf][1][nf][q] + c_bsz[nf][j];
                        float ghn = cfr[mf][2][nf][q] + c_bhn[nf][j];
                        float gn = c_bin[nf][j];
#pragma unroll
                        for (int jj = 0; jj < 5; jj++) {
                            gr += xv[jj] * WihS[c * 5 + jj];
                            gz += xv[jj] * WihS[(c + 128) * 5 + jj];
                            gn += xv[jj] * WihS[(c + 256) * 5 + jj];
                        }
                        float rr = sigf(gr);
                        float zz = sigf(gz);
                        float nn = tanhfast(gn + rr * ghn);
                        hold[mf][nf][qr][j] =
                            (1.f - zz) * nn + zz * hold[mf][nf][qr][j];
                    }
            }
        }

        if (t + 1 < SS && tid < 160) {
            int row = tid / 5, b = b0 + row;
            xsb[((t + 1) & 1) * 160 + tid] =
                (row < E_RPB && b < BB) ? x[(long)b * (SS * 5) + (t + 1) * 5 + (tid % 5)]
                                        : 0.f;
        }
        __syncthreads();

#pragma unroll
        for (int mf = 0; mf < 2; mf++)
#pragma unroll
            for (int qr = 0; qr < 2; qr++)
#pragma unroll
                for (int nf = 0; nf < 2; nf++) {
                    int row = mf * 16 + (lane >> 2) + qr * 8;
                    int c0 = cl[nf][0];
                    float h0 = hold[mf][nf][qr][0], h1 = hold[mf][nf][qr][1];
                    float h0h = __bfloat162float(__float2bfloat16_rn(h0));
                    float h1h = __bfloat162float(__float2bfloat16_rn(h1));
                    int slab = c0 >> 6;
                    unsigned byte = (unsigned)(row * 128 + (c0 & 63) * 2);
                    unsigned sw = SW128(byte);
                    *(uint32_t*)(smem + EA_HI + slab * 4096 + sw) = pack2_bf16(h0h, h1h);
                    *(uint32_t*)(smem + EA_LO + slab * 4096 + sw) =
                        pack2_bf16(h0 - h0h, h1 - h1h);
                }
        __syncthreads();
    }

#pragma unroll
    for (int mf = 0; mf < 2; mf++)
#pragma unroll
        for (int qr = 0; qr < 2; qr++) {
            int row = mf * 16 + (lane >> 2) + qr * 8;
            if (row < E_RPB && b0 + row < BB) {
#pragma unroll
                for (int nf = 0; nf < 2; nf++) {
                    *(float2*)(g_ctx + (long)(b0 + row) * 128 + cl[nf][0]) =
                        make_float2(hold[mf][nf][qr][0], hold[mf][nf][qr][1]);
                }
            }
        }
}

// ---------------------------------------------------------------------------
// init
// ---------------------------------------------------------------------------
__global__ void init_kernel(const float* __restrict__ Whh, float* __restrict__ out) {
    const float4 one4 = make_float4(1.f, 1.f, 1.f, 1.f);
    int i = blockIdx.x * blockDim.x + threadIdx.x;
    if (i < BB * DH / 4) ((float4*)g_h)[i] = one4;
    if (i < BB * DH) {
        g_hb_hi[i] = __float2bfloat16(1.f);
        g_hb_lo[i] = __float2bfloat16(0.f);
    }
    if (i < 768 * DH) {
        float w = Whh[i];
        __nv_bfloat16 hi = __float2bfloat16(w);
        g_wb_hi[i] = hi;
        g_wb_lo[i] = __float2bfloat16(w - __bfloat162float(hi));
    }
    if (i < BB * 118) {
        int b = i / 118, tt = i % 118 + NDEC;
        *(float4*)(out + (long)b * (SS * 4) + tt * 4) = one4;
    }
}

// ---------------------------------------------------------------------------
// gi0 (once), scalar
// ---------------------------------------------------------------------------
#define NG 24
#define RPG 171
#define GI_WSTR 132
#define GI_SMEM_BYTES ((128 * GI_WSTR + 64 * 128) * 4)

__global__ void __launch_bounds__(256, 1)
dec_gi0_kernel(const float* __restrict__ Wih, const float* __restrict__ bih)
{
    extern __shared__ float sm[];
    float* Ws = sm;
    float* hs = sm + 128 * GI_WSTR;

    const int tid = threadIdx.x;
    const int s = blockIdx.x / NG;
    const int g = blockIdx.x % NG;
    const int r0 = g * RPG;
    const int nr = min(RPG, BB - r0);

    for (int u = tid; u < 128 * 128; u += 256) {
        int c = u >> 7, k = u & 127;
        Ws[c * GI_WSTR + k] = Wih[(long)(s * 128 + c) * 129 + k];
    }
    __syncthreads();

    const int rg = tid >> 5, cg = tid & 31;
    float bv[4];
#pragma unroll
    for (int m = 0; m < 4; m++) bv[m] = bih[s * 128 + cg + 32 * m];

    const int nchunk = (nr + 63) >> 6;
    for (int ch = 0; ch < nchunk; ++ch) {
        int rbase = ch * 64;
        for (int u = tid; u < 64 * 32; u += 256) {
            int r = u >> 5, q = u & 31;
            float4 v = make_float4(0.f, 0.f, 0.f, 0.f);
            if (rbase + r < nr)
                v = *(const float4*)(g_ctx + (long)(r0 + rbase + r) * 128 + q * 4);
            *(float4*)(hs + r * 128 + q * 4) = v;
        }
        __syncthreads();

        u64 acc[8][4];
#pragma unroll
        for (int i = 0; i < 8; i++)
#pragma unroll
            for (int m = 0; m < 4; m++) acc[i][m] = 0ULL;

#pragma unroll 2
        for (int kq = 0; kq < 32; ++kq) {
            ulonglong2 w[4];
#pragma unroll
            for (int m = 0; m < 4; m++)
                w[m] = *(const ulonglong2*)(Ws + (cg + 32 * m) * GI_WSTR + kq * 4);
#pragma unroll
            for (int i = 0; i < 8; i++) {
                ulonglong2 hv = *(const ulonglong2*)(hs + (rg * 8 + i) * 128 + kq * 4);
#pragma unroll
                for (int m = 0; m < 4; m++) {
                    ffma2(hv.x, w[m].x, acc[i][m]);
                    ffma2(hv.y, w[m].y, acc[i][m]);
                }
            }
        }
#pragma unroll
        for (int i = 0; i < 8; i++) {
            int row = rbase + rg * 8 + i;
            if (row < nr) {
#pragma unroll
                for (int m = 0; m < 4; m++)
                    g_gi0[(long)(r0 + row) * 768 + s * 128 + cg + 32 * m] =
                        f2sum(acc[i][m]) + bv[m];
            }
        }
        __syncthreads();
    }
}

// ---------------------------------------------------------------------------
// Decoder GEMM via mma.sync. R17: N-tile 96 -> grid 32x8=256 = single wave
// at 2 blocks/SM (was 384 = 1.3 waves). k-chunked (4 x k=64), smem ~63KB.
// 512 threads; warp tile 32x24 (mf 2 x nf 3).
// ---------------------------------------------------------------------------
#define MM_STR 72                      // bf16 per padded row (k-chunk 64)
#define MM_A_HI 0
#define MM_A_LO (MM_A_HI + 128 * MM_STR * 2)
#define MM_B_HI (MM_A_LO + 128 * MM_STR * 2)
#define MM_B_LO (MM_B_HI + 96 * MM_STR * 2)
#define MM_SMEM_BYTES (MM_B_LO + 96 * MM_STR * 2)

__global__ void __launch_bounds__(512, 2)
dec_gemm_mma_kernel()
{
    extern __shared__ char smem[];
    const unsigned sb = smem_u32(smem);
    const int tid = threadIdx.x;
    const int lane = tid & 31;
    const int wid = tid >> 5;
    const int warp_m = wid & 3;        // 4 warps over M (32 rows each)
    const int warp_n = wid >> 2;       // 4 warps over N (24 cols each)
    const int mt = blockIdx.x & 31;
    const int nt = blockIdx.x >> 5;    // 0..7
    const int r0 = mt * 128;
    const int n0 = nt * 96;

    float c[2][3][4];
#pragma unroll
    for (int mf = 0; mf < 2; mf++)
#pragma unroll
        for (int nf = 0; nf < 3; nf++)
#pragma unroll
            for (int q = 0; q < 4; q++) c[mf][nf][q] = 0.f;

    const unsigned a_row = (unsigned)(warp_m * 32 + (lane & 15));
    const unsigned a_half = (unsigned)((lane >> 4) * 16);
    const unsigned b_row = (unsigned)(warp_n * 24 + (lane & 7));
    const unsigned b_half = (unsigned)(((lane >> 3) & 1) * 16);

    for (int kc = 0; kc < 4; ++kc) {
        // stage A: 128 rows x 8 segs of 16B (64 bf16)
        for (int u = tid; u < 128 * 8; u += 512) {
            int row = u >> 3, seg = u & 7;
            unsigned off = (unsigned)(row * (MM_STR * 2) + seg * 16);
            long src = (long)(r0 + row) * 256 + kc * 64 + seg * 8;
            *(uint4*)(smem + MM_A_HI + off) = *(const uint4*)(g_hb_hi + src);
            *(uint4*)(smem + MM_A_LO + off) = *(const uint4*)(g_hb_lo + src);
        }
        // stage B: 96 rows x 8 segs
        for (int u = tid; u < 96 * 8; u += 512) {
            int row = u >> 3, seg = u & 7;
            unsigned off = (unsigned)(row * (MM_STR * 2) + seg * 16);
            long src = (long)(n0 + row) * 256 + kc * 64 + seg * 8;
            *(uint4*)(smem + MM_B_HI + off) = *(const uint4*)(g_wb_hi + src);
            *(uint4*)(smem + MM_B_LO + off) = *(const uint4*)(g_wb_lo + src);
        }
        __syncthreads();

#pragma unroll
        for (int kk = 0; kk < 4; ++kk) {
            const unsigned koff = (unsigned)(kk * 32);
            uint32_t bh[3][2], bl[3][2];
#pragma unroll
            for (int nf = 0; nf < 3; nf++) {
                unsigned ba = (b_row + nf * 8) * (MM_STR * 2) + koff + b_half;
                ldsm_x2(bh[nf], sb + MM_B_HI + ba);
                ldsm_x2(bl[nf], sb + MM_B_LO + ba);
            }
#pragma unroll
            for (int mf = 0; mf < 2; mf++) {
                unsigned aa = (a_row + mf * 16) * (MM_STR * 2) + koff + a_half;
                uint32_t ah[4], al[4];
                ldsm_x4(ah, sb + MM_A_HI + aa);
                ldsm_x4(al, sb + MM_A_LO + aa);
#pragma unroll
                for (int nf = 0; nf < 3; nf++) {
                    mma_bf16(c[mf][nf], ah, bh[nf]);
                    mma_bf16(c[mf][nf], ah, bl[nf]);
                    mma_bf16(c[mf][nf], al, bh[nf]);
                }
            }
        }
        __syncthreads();
    }

#pragma unroll
    for (int mf = 0; mf < 2; mf++) {
#pragma unroll
        for (int nf = 0; nf < 3; nf++) {
            int row = r0 + warp_m * 32 + mf * 16 + (lane >> 2);
            int col = n0 + warp_n * 24 + nf * 8 + (lane & 3) * 2;
            *(float2*)(g_gates + (long)row * 768 + col) =
                make_float2(c[mf][nf][0], c[mf][nf][1]);
            *(float2*)(g_gates + (long)(row + 8) * 768 + col) =
                make_float2(c[mf][nf][2], c[mf][nf][3]);
        }
    }
}

// ---------------------------------------------------------------------------
// pointwise
// ---------------------------------------------------------------------------
__global__ void __launch_bounds__(256, 1)
dec_point_kernel(const float* __restrict__ y, const float* __restrict__ Wih,
                 const float* __restrict__ bhh, const float* __restrict__ linW,
                 const float* __restrict__ linb, float* __restrict__ out, int t)
{
    __shared__ float hs[32 * 256];
    __shared__ float ys[32];
    __shared__ float lw[1024];
    __shared__ float lb[4];

    const int tid = threadIdx.x;
    const int b0 = blockIdx.x * 32;

    if (tid < 32) ys[tid] = y[(long)(b0 + tid) * SS + t];
    for (int u = tid; u < 1024; u += 256) lw[u] = linW[u];
    if (tid < 4) lb[tid] = linb[tid];

    const int c = tid;
    const float wyr = Wih[(long)c * 129 + 128];
    const float wyz = Wih[(long)(c + 256) * 129 + 128];
    const float wyn = Wih[(long)(c + 512) * 129 + 128];
    const float br = bhh[c], bz = bhh[c + 256], bn = bhh[c + 512];
    __syncthreads();

#pragma unroll 4
    for (int r = 0; r < 32; ++r) {
        long b = b0 + r;
        float yv = ys[r];
        float gr  = g_gi0[b * 768 + c]       + yv * wyr + g_gates[b * 768 + c]       + br;
        float gz  = g_gi0[b * 768 + c + 256] + yv * wyz + g_gates[b * 768 + c + 256] + bz;
        float gni = g_gi0[b * 768 + c + 512] + yv * wyn;
        float gnh = g_gates[b * 768 + c + 512] + bn;
        float rr = sigf(gr);
        float zz = sigf(gz);
        float nn = tanhfast(gni + rr * gnh);
        float h  = g_h[b * 256 + c];
        float hn = (1.f - zz) * nn + zz * h;
        g_h[b * 256 + c] = hn;
        __nv_bfloat16 hi = __float2bfloat16(hn);
        g_hb_hi[b * 256 + c] = hi;
        g_hb_lo[b * 256 + c] = __float2bfloat16(hn - __bfloat162float(hi));
        hs[r * 256 + c] = hn;
    }
    __syncthreads();

    if (tid < 128) {
        int r = tid >> 2, o = tid & 3;
        float s = lb[o];
#pragma unroll 4
        for (int q = 0; q < 64; ++q) {
            float4 hv = *(float4*)(hs + r * 256 + q * 4);
            float4 wv = *(float4*)(lw + o * 256 + q * 4);
            s += hv.x * wv.x + hv.y * wv.y + hv.z * wv.z + hv.w * wv.w;
        }
        out[(long)(b0 + r) * (SS * 4) + t * 4 + o] = s;
    }
}

extern "C" void kernel_launch(void* const* d_in, const int* in_sizes, int n_in,
                              void* d_out, int out_size) {
    const float* x    = (const float*)d_in[0];
    const float* y    = (const float*)d_in[1];
    const float* eWih = (const float*)d_in[2];
    const float* eWhh = (const float*)d_in[3];
    const float* ebih = (const float*)d_in[4];
    const float* ebhh = (const float*)d_in[5];
    const float* dWih = (const float*)d_in[6];
    const float* dWhh = (const float*)d_in[7];
    const float* dbih = (const float*)d_in[8];
    const float* dbhh = (const float*)d_in[9];
    const float* lW   = (const float*)d_in[10];
    const float* lb   = (const float*)d_in[11];
    float* out = (float*)d_out;

    cudaFuncSetAttribute(enc_tc_kernel, cudaFuncAttributeMaxDynamicSharedMemorySize,
                         E2_SMEM_BYTES);
    cudaFuncSetAttribute(dec_gi0_kernel, cudaFuncAttributeMaxDynamicSharedMemorySize,
                         GI_SMEM_BYTES);
    cudaFuncSetAttribute(dec_gemm_mma_kernel, cudaFuncAttributeMaxDynamicSharedMemorySize,
                         MM_SMEM_BYTES);

    init_kernel<<<BB, 256>>>(dWhh, out);                              // 1
    enc_tc_kernel<<<(BB + E_RPB - 1) / E_RPB, 256, E2_SMEM_BYTES>>>(  // 2
        x, eWih, eWhh, ebih, ebhh);
    dec_gi0_kernel<<<6 * NG, 256, GI_SMEM_BYTES>>>(dWih, dbih);       // 3
    for (int t = 0; t < NDEC; ++t) {
        dec_gemm_mma_kernel<<<256, 512, MM_SMEM_BYTES>>>();           // 4 <- ncu (t=0)
        dec_point_kernel<<<BB / 32, 256>>>(y, dWih, dbhh, lW, lb, out, t);
    }
}